// round 13
// baseline (speedup 1.0000x reference)
#include <cuda_runtime.h>
#include <cuda_bf16.h>
#include <cuda_fp16.h>
#include <cstdint>

// ---------------------------------------------------------------------------
// HybridForecaster: SNN(LIF) -> GRU -> linear head
// B=64, T=2048, C=64, H=256, HOR=96, BETA=0.9, THR=1.0
// R12: GRU dot = 112k fp32-reg (f32x2) + 144k fp16x2-reg (HFMA2 vs packed
//      fp16 h copy) -> zero weight-LDS traffic; smem 206KB -> ~12KB static.
// ---------------------------------------------------------------------------

#define Bb   64
#define Tt   2048
#define Cc   64
#define Hh   256
#define G3   768
#define KA   320
#define HORd 96
#define BT   (Bb * Tt)

__device__ float g_cur[(size_t)BT * Hh];                 // 134 MB
__device__ __nv_bfloat16 g_a [(size_t)BT * KA];          // 84 MB  [x|spk] hi
__device__ __nv_bfloat16 g_al[(size_t)BT * Cc];          // 17 MB  x lo
__device__ __nv_bfloat16 g_wh[(size_t)G3 * KA];          // wih hi
__device__ __nv_bfloat16 g_wl[(size_t)G3 * KA];          // wih lo
__device__ float g_gx [(size_t)BT * G3];                 // 402 MB
__device__ float g_hT [Bb * Hh];

// ------------------------- packed helpers ----------------------------------
__device__ __forceinline__ unsigned long long ffma2(
    unsigned long long a, unsigned long long b, unsigned long long c) {
  unsigned long long d;
  asm("fma.rn.f32x2 %0, %1, %2, %3;" : "=l"(d) : "l"(a), "l"(b), "l"(c));
  return d;
}
__device__ __forceinline__ void unpack2(unsigned long long v, float& lo,
                                        float& hi) {
  asm("mov.b64 {%0, %1}, %2;" : "=f"(lo), "=f"(hi) : "l"(v));
}
__device__ __forceinline__ unsigned bf16pack(float lo, float hi) {
  unsigned r;
  asm("cvt.rn.bf16x2.f32 %0, %1, %2;" : "=r"(r) : "f"(hi), "f"(lo));
  return r;
}
__device__ __forceinline__ unsigned smem_u32(const void* p) {
  return (unsigned)__cvta_generic_to_shared(p);
}
__device__ __forceinline__ void bfsplit(float x, __nv_bfloat16& hi,
                                        __nv_bfloat16& lo) {
  hi = __float2bfloat16(x);
  lo = __float2bfloat16(x - __bfloat162float(hi));
}

// ---------------------------------------------------------------------------
// K1: cur = x @ snn_w^T + snn_b  (fp32 — feeds threshold logic)
// ---------------------------------------------------------------------------
__global__ __launch_bounds__(256) void cur_gemm_kernel(
    const float* __restrict__ x, const float* __restrict__ w,
    const float* __restrict__ bias) {
  __shared__ float As[32][130];
  __shared__ float Bs[32][66];
  const int row0 = blockIdx.x * 128;
  const int col0 = blockIdx.y * 64;
  const int tid  = threadIdx.x;
  const int tm   = tid & 15;
  const int tn   = tid >> 4;
  float acc[8][4];
#pragma unroll
  for (int i = 0; i < 8; i++)
#pragma unroll
    for (int j = 0; j < 4; j++) acc[i][j] = 0.f;

  const int lm = tid >> 3;
  const int lk = (tid & 7) << 2;

  for (int k0 = 0; k0 < 64; k0 += 32) {
#pragma unroll
    for (int i = 0; i < 4; i++) {
      int m = lm + 32 * i;
      float4 v = *reinterpret_cast<const float4*>(
          &x[(size_t)(row0 + m) * Cc + k0 + lk]);
      As[lk + 0][m] = v.x; As[lk + 1][m] = v.y;
      As[lk + 2][m] = v.z; As[lk + 3][m] = v.w;
    }
#pragma unroll
    for (int i = 0; i < 2; i++) {
      int n = lm + 32 * i;
      float4 v = *reinterpret_cast<const float4*>(
          &w[(size_t)(col0 + n) * Cc + k0 + lk]);
      Bs[lk + 0][n] = v.x; Bs[lk + 1][n] = v.y;
      Bs[lk + 2][n] = v.z; Bs[lk + 3][n] = v.w;
    }
    __syncthreads();
#pragma unroll
    for (int kk = 0; kk < 32; kk++) {
      float a[8], b[4];
#pragma unroll
      for (int i = 0; i < 8; i++) a[i] = As[kk][tm + 16 * i];
#pragma unroll
      for (int j = 0; j < 4; j++) b[j] = Bs[kk][tn * 4 + j];
#pragma unroll
      for (int i = 0; i < 8; i++)
#pragma unroll
        for (int j = 0; j < 4; j++) acc[i][j] += a[i] * b[j];
    }
    __syncthreads();
  }
  float4 bv = *reinterpret_cast<const float4*>(&bias[col0 + tn * 4]);
#pragma unroll
  for (int i = 0; i < 8; i++) {
    float4 o;
    o.x = acc[i][0] + bv.x; o.y = acc[i][1] + bv.y;
    o.z = acc[i][2] + bv.z; o.w = acc[i][3] + bv.w;
    *reinterpret_cast<float4*>(
        &g_cur[(size_t)(row0 + tm + 16 * i) * Hh + col0 + tn * 4]) = o;
  }
}

// ---------------------------------------------------------------------------
// K2a: x -> bf16 hi into g_a[:,0:64], lo into g_al
// ---------------------------------------------------------------------------
__global__ __launch_bounds__(256) void xcvt_kernel(const float* __restrict__ x) {
  int idx8 = blockIdx.x * 256 + threadIdx.x;
  int row = idx8 >> 3;
  int c8  = (idx8 & 7) << 3;
  float v[8];
  *reinterpret_cast<float4*>(v) =
      *reinterpret_cast<const float4*>(&x[(size_t)row * Cc + c8]);
  *reinterpret_cast<float4*>(v + 4) =
      *reinterpret_cast<const float4*>(&x[(size_t)row * Cc + c8 + 4]);
  __nv_bfloat16 hi[8], lo[8];
#pragma unroll
  for (int i = 0; i < 8; i++) bfsplit(v[i], hi[i], lo[i]);
  *reinterpret_cast<uint4*>(&g_a [(size_t)row * KA + c8]) =
      *reinterpret_cast<uint4*>(hi);
  *reinterpret_cast<uint4*>(&g_al[(size_t)row * Cc + c8]) =
      *reinterpret_cast<uint4*>(lo);
}

// K2b: wih -> bf16 hi/lo
__global__ __launch_bounds__(256) void wcvt_kernel(
    const float* __restrict__ wih) {
  int idx8 = blockIdx.x * 256 + threadIdx.x;
  int base = idx8 << 3;
  float v[8];
  *reinterpret_cast<float4*>(v) =
      *reinterpret_cast<const float4*>(&wih[base]);
  *reinterpret_cast<float4*>(v + 4) =
      *reinterpret_cast<const float4*>(&wih[base + 4]);
  __nv_bfloat16 hi[8], lo[8];
#pragma unroll
  for (int i = 0; i < 8; i++) bfsplit(v[i], hi[i], lo[i]);
  *reinterpret_cast<uint4*>(&g_wh[base]) = *reinterpret_cast<uint4*>(hi);
  *reinterpret_cast<uint4*>(&g_wl[base]) = *reinterpret_cast<uint4*>(lo);
}

// ---------------------------------------------------------------------------
// K3: LIF scan -> bf16 spikes into g_a[:,64:320]. 128 blocks x 128 threads.
// ---------------------------------------------------------------------------
__global__ __launch_bounds__(128) void lif_kernel() {
  const int b = blockIdx.x >> 1;
  const int h = ((blockIdx.x & 1) << 7) + threadIdx.x;
  const float* cp = g_cur + (size_t)b * Tt * Hh + h;
  __nv_bfloat16* sp = g_a + (size_t)b * Tt * KA + 64 + h;
  const __nv_bfloat16 one = __float2bfloat16(1.0f);
  const __nv_bfloat16 zero = __float2bfloat16(0.0f);
  float mem = 0.f;
#pragma unroll 1
  for (int t = 0; t < Tt; t += 16) {
    float v[16];
#pragma unroll
    for (int i = 0; i < 16; i++) v[i] = __ldcs(cp + (size_t)(t + i) * Hh);
#pragma unroll
    for (int i = 0; i < 16; i++) {
      float reset = (mem > 1.0f) ? 1.0f : 0.0f;
      mem = 0.9f * mem + v[i] - reset;
      sp[(size_t)(t + i) * KA] = (mem > 1.0f) ? one : zero;
    }
  }
}

// ---------------------------------------------------------------------------
// K4: gx split-precision MMA (M=BT, N=768, K=320)  [unchanged from R11]
// ---------------------------------------------------------------------------
#define APAD 40
__global__ __launch_bounds__(256) void gx_mma_kernel(
    const float* __restrict__ bih) {
  __shared__ __nv_bfloat16 As [128][APAD];
  __shared__ __nv_bfloat16 Asl[128][APAD];
  __shared__ __nv_bfloat16 Bh [64][APAD];
  __shared__ __nv_bfloat16 Bl [64][APAD];
  const int col0 = blockIdx.x * 64;
  const int row0 = blockIdx.y * 128;
  const int tid  = threadIdx.x;
  const int warp = tid >> 5;
  const int lane = tid & 31;
  const int wm = warp & 3;
  const int wn = warp >> 2;

  float acc[2][4][4];
#pragma unroll
  for (int mi = 0; mi < 2; mi++)
#pragma unroll
    for (int ni = 0; ni < 4; ni++)
#pragma unroll
      for (int r = 0; r < 4; r++) acc[mi][ni][r] = 0.f;

  const int lmat = lane >> 3, lr = lane & 7;
  const int a_row_base = wm * 32 + lr + (lmat & 1) * 8;
  const int a_col_off  = (lmat >> 1) * 8;
  const int b_row_base = wn * 32 + (lmat >> 1) * 8 + lr;
  const int b_col_off  = (lmat & 1) * 8;

  uint4 rga[2], rgal[2], rgbh, rgbl;
  const int gr = tid >> 2, gqc = tid & 3;
  auto loadg = [&](int kt) {
    int k0 = kt * 32;
#pragma unroll
    for (int i = 0; i < 2; i++) {
      int q = tid + i * 256;
      int r = q >> 2, qc = q & 3;
      rga[i] = *reinterpret_cast<const uint4*>(
          &g_a[(size_t)(row0 + r) * KA + k0 + qc * 8]);
      if (kt < 2)
        rgal[i] = *reinterpret_cast<const uint4*>(
            &g_al[(size_t)(row0 + r) * Cc + k0 + qc * 8]);
    }
    rgbh = *reinterpret_cast<const uint4*>(
        &g_wh[(size_t)(col0 + gr) * KA + k0 + gqc * 8]);
    rgbl = *reinterpret_cast<const uint4*>(
        &g_wl[(size_t)(col0 + gr) * KA + k0 + gqc * 8]);
  };

  loadg(0);
#pragma unroll 1
  for (int kt = 0; kt < 10; kt++) {
    __syncthreads();
#pragma unroll
    for (int i = 0; i < 2; i++) {
      int q = tid + i * 256;
      int r = q >> 2, qc = q & 3;
      *reinterpret_cast<uint4*>(&As[r][qc * 8]) = rga[i];
      if (kt < 2) *reinterpret_cast<uint4*>(&Asl[r][qc * 8]) = rgal[i];
    }
    *reinterpret_cast<uint4*>(&Bh[gr][gqc * 8]) = rgbh;
    *reinterpret_cast<uint4*>(&Bl[gr][gqc * 8]) = rgbl;
    __syncthreads();
    if (kt < 9) loadg(kt + 1);

#pragma unroll
    for (int k0 = 0; k0 < 32; k0 += 16) {
      unsigned a[2][4], bh[2][4], bl[2][4];
#pragma unroll
      for (int mi = 0; mi < 2; mi++) {
        unsigned addr = smem_u32(&As[a_row_base + mi * 16][k0 + a_col_off]);
        asm volatile(
            "ldmatrix.sync.aligned.m8n8.x4.shared.b16 {%0,%1,%2,%3}, [%4];"
            : "=r"(a[mi][0]), "=r"(a[mi][1]), "=r"(a[mi][2]), "=r"(a[mi][3])
            : "r"(addr));
      }
#pragma unroll
      for (int np = 0; np < 2; np++) {
        unsigned addr = smem_u32(&Bh[b_row_base + np * 16][k0 + b_col_off]);
        asm volatile(
            "ldmatrix.sync.aligned.m8n8.x4.shared.b16 {%0,%1,%2,%3}, [%4];"
            : "=r"(bh[np][0]), "=r"(bh[np][1]), "=r"(bh[np][2]),
              "=r"(bh[np][3])
            : "r"(addr));
        unsigned addr2 = smem_u32(&Bl[b_row_base + np * 16][k0 + b_col_off]);
        asm volatile(
            "ldmatrix.sync.aligned.m8n8.x4.shared.b16 {%0,%1,%2,%3}, [%4];"
            : "=r"(bl[np][0]), "=r"(bl[np][1]), "=r"(bl[np][2]),
              "=r"(bl[np][3])
            : "r"(addr2));
      }
#pragma unroll
      for (int mi = 0; mi < 2; mi++)
#pragma unroll
        for (int ni = 0; ni < 4; ni++) {
          unsigned h0r = bh[ni >> 1][(ni & 1) * 2 + 0];
          unsigned h1r = bh[ni >> 1][(ni & 1) * 2 + 1];
          asm volatile(
              "mma.sync.aligned.m16n8k16.row.col.f32.bf16.bf16.f32 "
              "{%0,%1,%2,%3}, {%4,%5,%6,%7}, {%8,%9}, {%0,%1,%2,%3};"
              : "+f"(acc[mi][ni][0]), "+f"(acc[mi][ni][1]),
                "+f"(acc[mi][ni][2]), "+f"(acc[mi][ni][3])
              : "r"(a[mi][0]), "r"(a[mi][1]), "r"(a[mi][2]), "r"(a[mi][3]),
                "r"(h0r), "r"(h1r));
          unsigned l0 = bl[ni >> 1][(ni & 1) * 2 + 0];
          unsigned l1 = bl[ni >> 1][(ni & 1) * 2 + 1];
          asm volatile(
              "mma.sync.aligned.m16n8k16.row.col.f32.bf16.bf16.f32 "
              "{%0,%1,%2,%3}, {%4,%5,%6,%7}, {%8,%9}, {%0,%1,%2,%3};"
              : "+f"(acc[mi][ni][0]), "+f"(acc[mi][ni][1]),
                "+f"(acc[mi][ni][2]), "+f"(acc[mi][ni][3])
              : "r"(a[mi][0]), "r"(a[mi][1]), "r"(a[mi][2]), "r"(a[mi][3]),
                "r"(l0), "r"(l1));
        }
      if (kt < 2) {
        unsigned al[2][4];
#pragma unroll
        for (int mi = 0; mi < 2; mi++) {
          unsigned addr =
              smem_u32(&Asl[a_row_base + mi * 16][k0 + a_col_off]);
          asm volatile(
              "ldmatrix.sync.aligned.m8n8.x4.shared.b16 {%0,%1,%2,%3}, [%4];"
              : "=r"(al[mi][0]), "=r"(al[mi][1]), "=r"(al[mi][2]),
                "=r"(al[mi][3])
              : "r"(addr));
        }
#pragma unroll
        for (int mi = 0; mi < 2; mi++)
#pragma unroll
          for (int ni = 0; ni < 4; ni++) {
            unsigned h0r = bh[ni >> 1][(ni & 1) * 2 + 0];
            unsigned h1r = bh[ni >> 1][(ni & 1) * 2 + 1];
            asm volatile(
                "mma.sync.aligned.m16n8k16.row.col.f32.bf16.bf16.f32 "
                "{%0,%1,%2,%3}, {%4,%5,%6,%7}, {%8,%9}, {%0,%1,%2,%3};"
                : "+f"(acc[mi][ni][0]), "+f"(acc[mi][ni][1]),
                  "+f"(acc[mi][ni][2]), "+f"(acc[mi][ni][3])
                : "r"(al[mi][0]), "r"(al[mi][1]), "r"(al[mi][2]),
                  "r"(al[mi][3]), "r"(h0r), "r"(h1r));
          }
      }
    }
  }

  const int gp = lane >> 2, tg = lane & 3;
#pragma unroll
  for (int mi = 0; mi < 2; mi++) {
#pragma unroll
    for (int ni = 0; ni < 4; ni++) {
      int col = col0 + wn * 32 + ni * 8 + tg * 2;
      float bx = bih[col], by = bih[col + 1];
      int r0 = row0 + wm * 32 + mi * 16 + gp;
      float2 o0 = {acc[mi][ni][0] + bx, acc[mi][ni][1] + by};
      float2 o1 = {acc[mi][ni][2] + bx, acc[mi][ni][3] + by};
      *reinterpret_cast<float2*>(&g_gx[(size_t)r0 * G3 + col]) = o0;
      *reinterpret_cast<float2*>(&g_gx[(size_t)(r0 + 8) * G3 + col]) = o1;
    }
  }
}

// ---------------------------------------------------------------------------
// K5: GRU scan. cluster(2)/batch, 384 thr/CTA, 1 gate row/thread.
// Dot: k<112 fp32 regs via f32x2 FMA on fp32 h; k in [112,256) fp16x2 regs
// via HFMA2 on packed fp16 h copy. No weight LDS. Pre-activation exchange
// via DSMEM + mbarrier (R9 protocol); redundant gate math in both CTAs;
// gate phase maintains fp32 h AND fp16 h copies.
// ---------------------------------------------------------------------------
#define GRU_THREADS 384

__global__ void __cluster_dims__(2, 1, 1) __launch_bounds__(GRU_THREADS, 1)
gru_kernel(const float* __restrict__ whh, const float* __restrict__ bhh) {
  __shared__ float h0[256], h1[256];
  __shared__ __align__(16) __half hp0[256];
  __shared__ __align__(16) __half hp1[256];
  __shared__ float gh[2048];
  __shared__ __align__(16) unsigned long long mbar[2];

  const int tid = threadIdx.x;
  unsigned rank_u;
  asm("mov.u32 %0, %%cluster_ctarank;" : "=r"(rank_u));
  const int rank = (int)rank_u;
  const int peer = rank ^ 1;
  const int bidx = blockIdx.x >> 1;
  const int g = tid >> 7;
  const int d = tid & 127;
  const int gdim = rank * 128 + d;
  const int jg = g * 256 + gdim;

  const float* wr = whh + (size_t)jg * 256;

  // k<112: fp32 weights as 56 packed f32x2
  unsigned long long wreg[56];
#pragma unroll
  for (int i = 0; i < 28; i++) {
    ulonglong2 v = *reinterpret_cast<const ulonglong2*>(wr + i * 4);
    wreg[2 * i] = v.x; wreg[2 * i + 1] = v.y;
  }
  // k in [112,256): fp16x2 weights in 72 regs
  __half2 w16[72];
#pragma unroll
  for (int j = 0; j < 18; j++) {
    float4 a = *reinterpret_cast<const float4*>(wr + 112 + j * 8);
    float4 b = *reinterpret_cast<const float4*>(wr + 112 + j * 8 + 4);
    w16[4 * j + 0] = __floats2half2_rn(a.x, a.y);
    w16[4 * j + 1] = __floats2half2_rn(a.z, a.w);
    w16[4 * j + 2] = __floats2half2_rn(b.x, b.y);
    w16[4 * j + 3] = __floats2half2_rn(b.z, b.w);
  }

  const float bhh_j = bhh[jg];
  for (int i = tid; i < 256; i += GRU_THREADS) {
    h0[i] = 0.f;
    hp0[i] = __float2half(0.f);
  }

  const unsigned mb_base = smem_u32(&mbar[0]);
  if (tid == 0) {
    asm volatile("mbarrier.init.shared.b64 [%0], %1;" ::"r"(mb_base),
                 "r"(384u) : "memory");
    asm volatile("mbarrier.init.shared.b64 [%0], %1;" ::"r"(mb_base + 8),
                 "r"(384u) : "memory");
  }

  // per-thread gh slot (same offset both CTAs)
  const int off0 = (g == 2) ? (512 + 2 * gdim) : (g * 256 + gdim);
  float* lp0 = gh + off0;
  unsigned rgh0, rmb;
  {
    unsigned lgh = smem_u32(gh) + (unsigned)off0 * 4u;
    asm volatile("mapa.shared::cluster.u32 %0, %1, %2;"
                 : "=r"(rgh0) : "r"(lgh), "r"(peer));
    asm volatile("mapa.shared::cluster.u32 %0, %1, %2;"
                 : "=r"(rmb) : "r"(mb_base), "r"(peer));
  }

  __syncthreads();
  asm volatile("barrier.cluster.arrive.aligned;" ::: "memory");
  asm volatile("barrier.cluster.wait.aligned;" ::: "memory");

  const float* gxp = g_gx + (size_t)bidx * Tt * G3 + jg;
  float gxv = __ldcg(gxp);

  int ph0 = 0, ph1 = 0;

#pragma unroll 1
  for (int t = 0; t < Tt; t++) {
    const float* hr = (t & 1) ? h1 : h0;
    float* hw = (t & 1) ? h0 : h1;
    const __half* hpr = (t & 1) ? hp1 : hp0;
    __half* hpw = (t & 1) ? hp0 : hp1;
    const int buf = t & 1;
    float gxnext = (t + 1 < Tt) ? __ldcg(gxp + (size_t)(t + 1) * G3) : 0.f;

    // ---- fp32 part: k in [0,112) ----
    unsigned long long A0 = 0ull, A1 = 0ull, A2 = 0ull, A3 = 0ull;
#pragma unroll
    for (int i = 0; i < 14; i++) {
      ulonglong2 u = *reinterpret_cast<const ulonglong2*>(hr + i * 8);
      ulonglong2 v = *reinterpret_cast<const ulonglong2*>(hr + i * 8 + 4);
      A0 = ffma2(wreg[4 * i + 0], u.x, A0);
      A1 = ffma2(wreg[4 * i + 1], u.y, A1);
      A2 = ffma2(wreg[4 * i + 2], v.x, A2);
      A3 = ffma2(wreg[4 * i + 3], v.y, A3);
    }
    // ---- fp16 part: k in [112,256), HFMA2, 8 rotating accumulators ----
    __half2 hc[8];
#pragma unroll
    for (int i = 0; i < 8; i++) hc[i] = __float2half2_rn(0.f);
    const uint4* hp4 = reinterpret_cast<const uint4*>(hpr + 112);
#pragma unroll
    for (int i = 0; i < 18; i++) {
      uint4 hv = hp4[i];
      const int ai = (i & 1) * 4;
      hc[ai + 0] = __hfma2(w16[4 * i + 0],
                           *reinterpret_cast<__half2*>(&hv.x), hc[ai + 0]);
      hc[ai + 1] = __hfma2(w16[4 * i + 1],
                           *reinterpret_cast<__half2*>(&hv.y), hc[ai + 1]);
      hc[ai + 2] = __hfma2(w16[4 * i + 2],
                           *reinterpret_cast<__half2*>(&hv.z), hc[ai + 2]);
      hc[ai + 3] = __hfma2(w16[4 * i + 3],
                           *reinterpret_cast<__half2*>(&hv.w), hc[ai + 3]);
    }
    float p0, p1, p2, p3, p4, p5, p6, p7;
    unpack2(A0, p0, p1); unpack2(A1, p2, p3);
    unpack2(A2, p4, p5); unpack2(A3, p6, p7);
    float2 f0 = __half22float2(hc[0]);
    float2 f1 = __half22float2(hc[1]);
    float2 f2 = __half22float2(hc[2]);
    float2 f3 = __half22float2(hc[3]);
    float2 f4 = __half22float2(hc[4]);
    float2 f5 = __half22float2(hc[5]);
    float2 f6 = __half22float2(hc[6]);
    float2 f7 = __half22float2(hc[7]);
    float hsum = ((f0.x + f0.y) + (f1.x + f1.y)) +
                 ((f2.x + f2.y) + (f3.x + f3.y)) +
                 ((f4.x + f4.y) + (f5.x + f5.y)) +
                 ((f6.x + f6.y) + (f7.x + f7.y));
    float s = ((p0 + p1) + (p2 + p3)) + ((p4 + p5) + (p6 + p7)) + hsum +
              bhh_j;

    // ---- publish pre-activations (sigmoid for g<2) ----
    const unsigned boff = (unsigned)buf * 4096u;
    if (g == 2) {
      lp0[buf * 1024] = s;
      lp0[buf * 1024 + 1] = gxv;
      asm volatile("st.shared::cluster.f32 [%0], %1;"
                   :: "r"(rgh0 + boff), "f"(s) : "memory");
      asm volatile("st.shared::cluster.f32 [%0], %1;"
                   :: "r"(rgh0 + boff + 4u), "f"(gxv) : "memory");
    } else {
      float v = 1.f / (1.f + __expf(-(gxv + s)));
      lp0[buf * 1024] = v;
      asm volatile("st.shared::cluster.f32 [%0], %1;"
                   :: "r"(rgh0 + boff), "f"(v) : "memory");
    }
    asm volatile("mbarrier.arrive.release.cluster.shared::cluster.b64 _, [%0];"
                 :: "r"(rmb + 8u * (unsigned)buf) : "memory");
    gxv = gxnext;
    __syncthreads();

    // ---- wait for peer's 384 pre-activations ----
    {
      unsigned mb = mb_base + 8u * (unsigned)buf;
      unsigned par = (unsigned)(buf ? ph1 : ph0);
      asm volatile(
          "{\n\t.reg .pred P1;\n\t"
          "GRUW_%=:\n\t"
          "mbarrier.try_wait.parity.acquire.cluster.shared::cta.b64 P1, [%0], "
          "%1;\n\t"
          "@P1 bra GRUD_%=;\n\t"
          "bra GRUW_%=;\n\t"
          "GRUD_%=:\n\t}"
          :: "r"(mb), "r"(par) : "memory");
      if (buf) ph1 ^= 1; else ph0 ^= 1;
    }

    // ---- full gate math, redundantly in both CTAs (256 threads) ----
    if (tid < 256) {
      const float* ghb = gh + buf * 1024;
      float r  = ghb[tid];
      float z  = ghb[256 + tid];
      float hn = ghb[512 + 2 * tid];
      float xn = ghb[512 + 2 * tid + 1];
      float y = xn + r * hn;
      float e = __expf(2.f * y);
      float n = 1.f - __fdividef(2.f, e + 1.f);
      float hold = hr[tid];
      float hnew = (1.f - z) * n + z * hold;
      hw[tid] = hnew;
      hpw[tid] = __float2half(hnew);
    }
    __syncthreads();
  }

  if (rank == 0 && tid < 256) g_hT[bidx * Hh + tid] = h0[tid];

  asm volatile("barrier.cluster.arrive.aligned;" ::: "memory");
  asm volatile("barrier.cluster.wait.aligned;" ::: "memory");
}

// ---------------------------------------------------------------------------
// K6: head.
// ---------------------------------------------------------------------------
__global__ __launch_bounds__(96) void head_kernel(
    const float* __restrict__ head_w, const float* __restrict__ head_b,
    float* __restrict__ out) {
  const int b = blockIdx.x;
  const int o = threadIdx.x;
  const float* h = g_hT + b * Hh;
  const float* wr = head_w + o * Hh;
  float acc = 0.f;
#pragma unroll 8
  for (int k = 0; k < Hh; k++) acc += h[k] * wr[k];
  out[b * HORd + o] = acc + head_b[o];
}

// ---------------------------------------------------------------------------
extern "C" void kernel_launch(void* const* d_in, const int* in_sizes, int n_in,
                              void* d_out, int out_size) {
  const float* x      = (const float*)d_in[0];
  const float* snn_w  = (const float*)d_in[1];
  const float* snn_b  = (const float*)d_in[2];
  const float* wih    = (const float*)d_in[3];
  const float* whh    = (const float*)d_in[4];
  const float* bih    = (const float*)d_in[5];
  const float* bhh    = (const float*)d_in[6];
  const float* head_w = (const float*)d_in[7];
  const float* head_b = (const float*)d_in[8];
  float* out = (float*)d_out;

  cur_gemm_kernel<<<dim3(BT / 128, Hh / 64), 256>>>(x, snn_w, snn_b);
  xcvt_kernel<<<BT * 8 / 256, 256>>>(x);
  wcvt_kernel<<<G3 * KA / 8 / 256, 256>>>(wih);
  lif_kernel<<<128, 128>>>();
  gx_mma_kernel<<<dim3(G3 / 64, BT / 128), 256>>>(bih);
  gru_kernel<<<Bb * 2, GRU_THREADS>>>(whh, bhh);
  head_kernel<<<Bb, HORd>>>(head_w, head_b, out);
}

// round 14
// speedup vs baseline: 2.1762x; 2.1762x over previous
#include <cuda_runtime.h>
#include <cuda_bf16.h>
#include <cuda_fp16.h>
#include <cstdint>

// ---------------------------------------------------------------------------
// HybridForecaster: SNN(LIF) -> GRU -> linear head
// B=64, T=2048, C=64, H=256, HOR=96, BETA=0.9, THR=1.0
// R13: GRU dot fully in fp16: 256 weights as 128 half2 REGISTERS (fits the
//      170-reg/thread cap at 384 thr), h read as fp16 (32 LDS.128), 128
//      HFMA2. No weight LDS, no spill. lif reverted to 64x256 grid.
// ---------------------------------------------------------------------------

#define Bb   64
#define Tt   2048
#define Cc   64
#define Hh   256
#define G3   768
#define KA   320
#define HORd 96
#define BT   (Bb * Tt)

__device__ float g_cur[(size_t)BT * Hh];                 // 134 MB
__device__ __nv_bfloat16 g_a [(size_t)BT * KA];          // 84 MB  [x|spk] hi
__device__ __nv_bfloat16 g_al[(size_t)BT * Cc];          // 17 MB  x lo
__device__ __nv_bfloat16 g_wh[(size_t)G3 * KA];          // wih hi
__device__ __nv_bfloat16 g_wl[(size_t)G3 * KA];          // wih lo
__device__ float g_gx [(size_t)BT * G3];                 // 402 MB
__device__ float g_hT [Bb * Hh];

// ------------------------- helpers -----------------------------------------
__device__ __forceinline__ unsigned smem_u32(const void* p) {
  return (unsigned)__cvta_generic_to_shared(p);
}
__device__ __forceinline__ void bfsplit(float x, __nv_bfloat16& hi,
                                        __nv_bfloat16& lo) {
  hi = __float2bfloat16(x);
  lo = __float2bfloat16(x - __bfloat162float(hi));
}

// ---------------------------------------------------------------------------
// K1: cur = x @ snn_w^T + snn_b  (fp32 — feeds threshold logic)
// ---------------------------------------------------------------------------
__global__ __launch_bounds__(256) void cur_gemm_kernel(
    const float* __restrict__ x, const float* __restrict__ w,
    const float* __restrict__ bias) {
  __shared__ float As[32][130];
  __shared__ float Bs[32][66];
  const int row0 = blockIdx.x * 128;
  const int col0 = blockIdx.y * 64;
  const int tid  = threadIdx.x;
  const int tm   = tid & 15;
  const int tn   = tid >> 4;
  float acc[8][4];
#pragma unroll
  for (int i = 0; i < 8; i++)
#pragma unroll
    for (int j = 0; j < 4; j++) acc[i][j] = 0.f;

  const int lm = tid >> 3;
  const int lk = (tid & 7) << 2;

  for (int k0 = 0; k0 < 64; k0 += 32) {
#pragma unroll
    for (int i = 0; i < 4; i++) {
      int m = lm + 32 * i;
      float4 v = *reinterpret_cast<const float4*>(
          &x[(size_t)(row0 + m) * Cc + k0 + lk]);
      As[lk + 0][m] = v.x; As[lk + 1][m] = v.y;
      As[lk + 2][m] = v.z; As[lk + 3][m] = v.w;
    }
#pragma unroll
    for (int i = 0; i < 2; i++) {
      int n = lm + 32 * i;
      float4 v = *reinterpret_cast<const float4*>(
          &w[(size_t)(col0 + n) * Cc + k0 + lk]);
      Bs[lk + 0][n] = v.x; Bs[lk + 1][n] = v.y;
      Bs[lk + 2][n] = v.z; Bs[lk + 3][n] = v.w;
    }
    __syncthreads();
#pragma unroll
    for (int kk = 0; kk < 32; kk++) {
      float a[8], b[4];
#pragma unroll
      for (int i = 0; i < 8; i++) a[i] = As[kk][tm + 16 * i];
#pragma unroll
      for (int j = 0; j < 4; j++) b[j] = Bs[kk][tn * 4 + j];
#pragma unroll
      for (int i = 0; i < 8; i++)
#pragma unroll
        for (int j = 0; j < 4; j++) acc[i][j] += a[i] * b[j];
    }
    __syncthreads();
  }
  float4 bv = *reinterpret_cast<const float4*>(&bias[col0 + tn * 4]);
#pragma unroll
  for (int i = 0; i < 8; i++) {
    float4 o;
    o.x = acc[i][0] + bv.x; o.y = acc[i][1] + bv.y;
    o.z = acc[i][2] + bv.z; o.w = acc[i][3] + bv.w;
    *reinterpret_cast<float4*>(
        &g_cur[(size_t)(row0 + tm + 16 * i) * Hh + col0 + tn * 4]) = o;
  }
}

// ---------------------------------------------------------------------------
// K2a: x -> bf16 hi into g_a[:,0:64], lo into g_al
// ---------------------------------------------------------------------------
__global__ __launch_bounds__(256) void xcvt_kernel(const float* __restrict__ x) {
  int idx8 = blockIdx.x * 256 + threadIdx.x;
  int row = idx8 >> 3;
  int c8  = (idx8 & 7) << 3;
  float v[8];
  *reinterpret_cast<float4*>(v) =
      *reinterpret_cast<const float4*>(&x[(size_t)row * Cc + c8]);
  *reinterpret_cast<float4*>(v + 4) =
      *reinterpret_cast<const float4*>(&x[(size_t)row * Cc + c8 + 4]);
  __nv_bfloat16 hi[8], lo[8];
#pragma unroll
  for (int i = 0; i < 8; i++) bfsplit(v[i], hi[i], lo[i]);
  *reinterpret_cast<uint4*>(&g_a [(size_t)row * KA + c8]) =
      *reinterpret_cast<uint4*>(hi);
  *reinterpret_cast<uint4*>(&g_al[(size_t)row * Cc + c8]) =
      *reinterpret_cast<uint4*>(lo);
}

// K2b: wih -> bf16 hi/lo
__global__ __launch_bounds__(256) void wcvt_kernel(
    const float* __restrict__ wih) {
  int idx8 = blockIdx.x * 256 + threadIdx.x;
  int base = idx8 << 3;
  float v[8];
  *reinterpret_cast<float4*>(v) =
      *reinterpret_cast<const float4*>(&wih[base]);
  *reinterpret_cast<float4*>(v + 4) =
      *reinterpret_cast<const float4*>(&wih[base + 4]);
  __nv_bfloat16 hi[8], lo[8];
#pragma unroll
  for (int i = 0; i < 8; i++) bfsplit(v[i], hi[i], lo[i]);
  *reinterpret_cast<uint4*>(&g_wh[base]) = *reinterpret_cast<uint4*>(hi);
  *reinterpret_cast<uint4*>(&g_wl[base]) = *reinterpret_cast<uint4*>(lo);
}

// ---------------------------------------------------------------------------
// K3: LIF scan -> bf16 spikes into g_a[:,64:320]  (64 blocks x 256 thr)
// ---------------------------------------------------------------------------
__global__ __launch_bounds__(256) void lif_kernel() {
  const int b = blockIdx.x;
  const int h = threadIdx.x;
  const float* cp = g_cur + (size_t)b * Tt * Hh + h;
  __nv_bfloat16* sp = g_a + (size_t)b * Tt * KA + 64 + h;
  const __nv_bfloat16 one = __float2bfloat16(1.0f);
  const __nv_bfloat16 zero = __float2bfloat16(0.0f);
  float mem = 0.f;
#pragma unroll 1
  for (int t = 0; t < Tt; t += 16) {
    float v[16];
#pragma unroll
    for (int i = 0; i < 16; i++) v[i] = __ldcs(cp + (size_t)(t + i) * Hh);
#pragma unroll
    for (int i = 0; i < 16; i++) {
      float reset = (mem > 1.0f) ? 1.0f : 0.0f;
      mem = 0.9f * mem + v[i] - reset;
      sp[(size_t)(t + i) * KA] = (mem > 1.0f) ? one : zero;
    }
  }
}

// ---------------------------------------------------------------------------
// K4: gx split-precision MMA (M=BT, N=768, K=320)  [unchanged from R11]
// ---------------------------------------------------------------------------
#define APAD 40
__global__ __launch_bounds__(256) void gx_mma_kernel(
    const float* __restrict__ bih) {
  __shared__ __nv_bfloat16 As [128][APAD];
  __shared__ __nv_bfloat16 Asl[128][APAD];
  __shared__ __nv_bfloat16 Bh [64][APAD];
  __shared__ __nv_bfloat16 Bl [64][APAD];
  const int col0 = blockIdx.x * 64;
  const int row0 = blockIdx.y * 128;
  const int tid  = threadIdx.x;
  const int warp = tid >> 5;
  const int lane = tid & 31;
  const int wm = warp & 3;
  const int wn = warp >> 2;

  float acc[2][4][4];
#pragma unroll
  for (int mi = 0; mi < 2; mi++)
#pragma unroll
    for (int ni = 0; ni < 4; ni++)
#pragma unroll
      for (int r = 0; r < 4; r++) acc[mi][ni][r] = 0.f;

  const int lmat = lane >> 3, lr = lane & 7;
  const int a_row_base = wm * 32 + lr + (lmat & 1) * 8;
  const int a_col_off  = (lmat >> 1) * 8;
  const int b_row_base = wn * 32 + (lmat >> 1) * 8 + lr;
  const int b_col_off  = (lmat & 1) * 8;

  uint4 rga[2], rgal[2], rgbh, rgbl;
  const int gr = tid >> 2, gqc = tid & 3;
  auto loadg = [&](int kt) {
    int k0 = kt * 32;
#pragma unroll
    for (int i = 0; i < 2; i++) {
      int q = tid + i * 256;
      int r = q >> 2, qc = q & 3;
      rga[i] = *reinterpret_cast<const uint4*>(
          &g_a[(size_t)(row0 + r) * KA + k0 + qc * 8]);
      if (kt < 2)
        rgal[i] = *reinterpret_cast<const uint4*>(
            &g_al[(size_t)(row0 + r) * Cc + k0 + qc * 8]);
    }
    rgbh = *reinterpret_cast<const uint4*>(
        &g_wh[(size_t)(col0 + gr) * KA + k0 + gqc * 8]);
    rgbl = *reinterpret_cast<const uint4*>(
        &g_wl[(size_t)(col0 + gr) * KA + k0 + gqc * 8]);
  };

  loadg(0);
#pragma unroll 1
  for (int kt = 0; kt < 10; kt++) {
    __syncthreads();
#pragma unroll
    for (int i = 0; i < 2; i++) {
      int q = tid + i * 256;
      int r = q >> 2, qc = q & 3;
      *reinterpret_cast<uint4*>(&As[r][qc * 8]) = rga[i];
      if (kt < 2) *reinterpret_cast<uint4*>(&Asl[r][qc * 8]) = rgal[i];
    }
    *reinterpret_cast<uint4*>(&Bh[gr][gqc * 8]) = rgbh;
    *reinterpret_cast<uint4*>(&Bl[gr][gqc * 8]) = rgbl;
    __syncthreads();
    if (kt < 9) loadg(kt + 1);

#pragma unroll
    for (int k0 = 0; k0 < 32; k0 += 16) {
      unsigned a[2][4], bh[2][4], bl[2][4];
#pragma unroll
      for (int mi = 0; mi < 2; mi++) {
        unsigned addr = smem_u32(&As[a_row_base + mi * 16][k0 + a_col_off]);
        asm volatile(
            "ldmatrix.sync.aligned.m8n8.x4.shared.b16 {%0,%1,%2,%3}, [%4];"
            : "=r"(a[mi][0]), "=r"(a[mi][1]), "=r"(a[mi][2]), "=r"(a[mi][3])
            : "r"(addr));
      }
#pragma unroll
      for (int np = 0; np < 2; np++) {
        unsigned addr = smem_u32(&Bh[b_row_base + np * 16][k0 + b_col_off]);
        asm volatile(
            "ldmatrix.sync.aligned.m8n8.x4.shared.b16 {%0,%1,%2,%3}, [%4];"
            : "=r"(bh[np][0]), "=r"(bh[np][1]), "=r"(bh[np][2]),
              "=r"(bh[np][3])
            : "r"(addr));
        unsigned addr2 = smem_u32(&Bl[b_row_base + np * 16][k0 + b_col_off]);
        asm volatile(
            "ldmatrix.sync.aligned.m8n8.x4.shared.b16 {%0,%1,%2,%3}, [%4];"
            : "=r"(bl[np][0]), "=r"(bl[np][1]), "=r"(bl[np][2]),
              "=r"(bl[np][3])
            : "r"(addr2));
      }
#pragma unroll
      for (int mi = 0; mi < 2; mi++)
#pragma unroll
        for (int ni = 0; ni < 4; ni++) {
          unsigned h0r = bh[ni >> 1][(ni & 1) * 2 + 0];
          unsigned h1r = bh[ni >> 1][(ni & 1) * 2 + 1];
          asm volatile(
              "mma.sync.aligned.m16n8k16.row.col.f32.bf16.bf16.f32 "
              "{%0,%1,%2,%3}, {%4,%5,%6,%7}, {%8,%9}, {%0,%1,%2,%3};"
              : "+f"(acc[mi][ni][0]), "+f"(acc[mi][ni][1]),
                "+f"(acc[mi][ni][2]), "+f"(acc[mi][ni][3])
              : "r"(a[mi][0]), "r"(a[mi][1]), "r"(a[mi][2]), "r"(a[mi][3]),
                "r"(h0r), "r"(h1r));
          unsigned l0 = bl[ni >> 1][(ni & 1) * 2 + 0];
          unsigned l1 = bl[ni >> 1][(ni & 1) * 2 + 1];
          asm volatile(
              "mma.sync.aligned.m16n8k16.row.col.f32.bf16.bf16.f32 "
              "{%0,%1,%2,%3}, {%4,%5,%6,%7}, {%8,%9}, {%0,%1,%2,%3};"
              : "+f"(acc[mi][ni][0]), "+f"(acc[mi][ni][1]),
                "+f"(acc[mi][ni][2]), "+f"(acc[mi][ni][3])
              : "r"(a[mi][0]), "r"(a[mi][1]), "r"(a[mi][2]), "r"(a[mi][3]),
                "r"(l0), "r"(l1));
        }
      if (kt < 2) {
        unsigned al[2][4];
#pragma unroll
        for (int mi = 0; mi < 2; mi++) {
          unsigned addr =
              smem_u32(&Asl[a_row_base + mi * 16][k0 + a_col_off]);
          asm volatile(
              "ldmatrix.sync.aligned.m8n8.x4.shared.b16 {%0,%1,%2,%3}, [%4];"
              : "=r"(al[mi][0]), "=r"(al[mi][1]), "=r"(al[mi][2]),
                "=r"(al[mi][3])
              : "r"(addr));
        }
#pragma unroll
        for (int mi = 0; mi < 2; mi++)
#pragma unroll
          for (int ni = 0; ni < 4; ni++) {
            unsigned h0r = bh[ni >> 1][(ni & 1) * 2 + 0];
            unsigned h1r = bh[ni >> 1][(ni & 1) * 2 + 1];
            asm volatile(
                "mma.sync.aligned.m16n8k16.row.col.f32.bf16.bf16.f32 "
                "{%0,%1,%2,%3}, {%4,%5,%6,%7}, {%8,%9}, {%0,%1,%2,%3};"
                : "+f"(acc[mi][ni][0]), "+f"(acc[mi][ni][1]),
                  "+f"(acc[mi][ni][2]), "+f"(acc[mi][ni][3])
                : "r"(al[mi][0]), "r"(al[mi][1]), "r"(al[mi][2]),
                  "r"(al[mi][3]), "r"(h0r), "r"(h1r));
          }
      }
    }
  }

  const int gp = lane >> 2, tg = lane & 3;
#pragma unroll
  for (int mi = 0; mi < 2; mi++) {
#pragma unroll
    for (int ni = 0; ni < 4; ni++) {
      int col = col0 + wn * 32 + ni * 8 + tg * 2;
      float bx = bih[col], by = bih[col + 1];
      int r0 = row0 + wm * 32 + mi * 16 + gp;
      float2 o0 = {acc[mi][ni][0] + bx, acc[mi][ni][1] + by};
      float2 o1 = {acc[mi][ni][2] + bx, acc[mi][ni][3] + by};
      *reinterpret_cast<float2*>(&g_gx[(size_t)r0 * G3 + col]) = o0;
      *reinterpret_cast<float2*>(&g_gx[(size_t)(r0 + 8) * G3 + col]) = o1;
    }
  }
}

// ---------------------------------------------------------------------------
// K5: GRU scan. cluster(2)/batch, 384 thr/CTA, 1 gate row/thread.
// ALL 256 weights as 128 half2 REGISTERS; dot = 32 LDS.128 of fp16 h +
// 128 HFMA2 (4 rotating half2 accumulators). fp32 h kept for gate math.
// Pre-activation exchange via DSMEM + mbarrier (R9 protocol); redundant
// gate math in both CTAs. Reg budget ~161 < 65536/384 = 170 (no spill).
// ---------------------------------------------------------------------------
#define GRU_THREADS 384

__global__ void __cluster_dims__(2, 1, 1) __launch_bounds__(GRU_THREADS, 1)
gru_kernel(const float* __restrict__ whh, const float* __restrict__ bhh) {
  __shared__ float h0[256], h1[256];
  __shared__ __align__(16) __half hp0[256];
  __shared__ __align__(16) __half hp1[256];
  __shared__ float gh[2048];
  __shared__ __align__(16) unsigned long long mbar[2];

  const int tid = threadIdx.x;
  unsigned rank_u;
  asm("mov.u32 %0, %%cluster_ctarank;" : "=r"(rank_u));
  const int rank = (int)rank_u;
  const int peer = rank ^ 1;
  const int bidx = blockIdx.x >> 1;
  const int g = tid >> 7;
  const int d = tid & 127;
  const int gdim = rank * 128 + d;
  const int jg = g * 256 + gdim;

  const float* wr = whh + (size_t)jg * 256;

  // all 256 weights as 128 packed fp16x2 registers
  __half2 w16[128];
#pragma unroll
  for (int j = 0; j < 32; j++) {
    float4 a = *reinterpret_cast<const float4*>(wr + j * 8);
    float4 b = *reinterpret_cast<const float4*>(wr + j * 8 + 4);
    w16[4 * j + 0] = __floats2half2_rn(a.x, a.y);
    w16[4 * j + 1] = __floats2half2_rn(a.z, a.w);
    w16[4 * j + 2] = __floats2half2_rn(b.x, b.y);
    w16[4 * j + 3] = __floats2half2_rn(b.z, b.w);
  }

  const float bhh_j = bhh[jg];
  for (int i = tid; i < 256; i += GRU_THREADS) {
    h0[i] = 0.f;
    hp0[i] = __float2half(0.f);
  }

  const unsigned mb_base = smem_u32(&mbar[0]);
  if (tid == 0) {
    asm volatile("mbarrier.init.shared.b64 [%0], %1;" ::"r"(mb_base),
                 "r"(384u) : "memory");
    asm volatile("mbarrier.init.shared.b64 [%0], %1;" ::"r"(mb_base + 8),
                 "r"(384u) : "memory");
  }

  // per-thread gh slot (same offset both CTAs)
  const int off0 = (g == 2) ? (512 + 2 * gdim) : (g * 256 + gdim);
  float* lp0 = gh + off0;
  unsigned rgh0, rmb;
  {
    unsigned lgh = smem_u32(gh) + (unsigned)off0 * 4u;
    asm volatile("mapa.shared::cluster.u32 %0, %1, %2;"
                 : "=r"(rgh0) : "r"(lgh), "r"(peer));
    asm volatile("mapa.shared::cluster.u32 %0, %1, %2;"
                 : "=r"(rmb) : "r"(mb_base), "r"(peer));
  }

  __syncthreads();
  asm volatile("barrier.cluster.arrive.aligned;" ::: "memory");
  asm volatile("barrier.cluster.wait.aligned;" ::: "memory");

  const float* gxp = g_gx + (size_t)bidx * Tt * G3 + jg;
  float gxv = __ldcg(gxp);

  int ph0 = 0, ph1 = 0;

#pragma unroll 1
  for (int t = 0; t < Tt; t++) {
    const float* hr = (t & 1) ? h1 : h0;
    float* hw = (t & 1) ? h0 : h1;
    const __half* hpr = (t & 1) ? hp1 : hp0;
    __half* hpw = (t & 1) ? hp0 : hp1;
    const int buf = t & 1;
    float gxnext = (t + 1 < Tt) ? __ldcg(gxp + (size_t)(t + 1) * G3) : 0.f;

    // ---- full 256-k dot in fp16: 32 LDS.128 + 128 HFMA2 ----
    __half2 hc0 = __float2half2_rn(0.f), hc1 = hc0, hc2 = hc0, hc3 = hc0;
    const uint4* hp4 = reinterpret_cast<const uint4*>(hpr);
#pragma unroll
    for (int i = 0; i < 32; i++) {
      uint4 hv = hp4[i];
      hc0 = __hfma2(w16[4 * i + 0], *reinterpret_cast<__half2*>(&hv.x), hc0);
      hc1 = __hfma2(w16[4 * i + 1], *reinterpret_cast<__half2*>(&hv.y), hc1);
      hc2 = __hfma2(w16[4 * i + 2], *reinterpret_cast<__half2*>(&hv.z), hc2);
      hc3 = __hfma2(w16[4 * i + 3], *reinterpret_cast<__half2*>(&hv.w), hc3);
    }
    float2 f0 = __half22float2(hc0);
    float2 f1 = __half22float2(hc1);
    float2 f2 = __half22float2(hc2);
    float2 f3 = __half22float2(hc3);
    float s = ((f0.x + f0.y) + (f1.x + f1.y)) +
              ((f2.x + f2.y) + (f3.x + f3.y)) + bhh_j;

    // ---- publish pre-activations (sigmoid for g<2) ----
    const unsigned boff = (unsigned)buf * 4096u;
    if (g == 2) {
      lp0[buf * 1024] = s;
      lp0[buf * 1024 + 1] = gxv;
      asm volatile("st.shared::cluster.f32 [%0], %1;"
                   :: "r"(rgh0 + boff), "f"(s) : "memory");
      asm volatile("st.shared::cluster.f32 [%0], %1;"
                   :: "r"(rgh0 + boff + 4u), "f"(gxv) : "memory");
    } else {
      float v = 1.f / (1.f + __expf(-(gxv + s)));
      lp0[buf * 1024] = v;
      asm volatile("st.shared::cluster.f32 [%0], %1;"
                   :: "r"(rgh0 + boff), "f"(v) : "memory");
    }
    asm volatile("mbarrier.arrive.release.cluster.shared::cluster.b64 _, [%0];"
                 :: "r"(rmb + 8u * (unsigned)buf) : "memory");
    gxv = gxnext;
    __syncthreads();

    // ---- wait for peer's 384 pre-activations ----
    {
      unsigned mb = mb_base + 8u * (unsigned)buf;
      unsigned par = (unsigned)(buf ? ph1 : ph0);
      asm volatile(
          "{\n\t.reg .pred P1;\n\t"
          "GRUW_%=:\n\t"
          "mbarrier.try_wait.parity.acquire.cluster.shared::cta.b64 P1, [%0], "
          "%1;\n\t"
          "@P1 bra GRUD_%=;\n\t"
          "bra GRUW_%=;\n\t"
          "GRUD_%=:\n\t}"
          :: "r"(mb), "r"(par) : "memory");
      if (buf) ph1 ^= 1; else ph0 ^= 1;
    }

    // ---- full gate math, redundantly in both CTAs (256 threads) ----
    if (tid < 256) {
      const float* ghb = gh + buf * 1024;
      float r  = ghb[tid];
      float z  = ghb[256 + tid];
      float hn = ghb[512 + 2 * tid];
      float xn = ghb[512 + 2 * tid + 1];
      float y = xn + r * hn;
      float e = __expf(2.f * y);
      float n = 1.f - __fdividef(2.f, e + 1.f);
      float hold = hr[tid];
      float hnew = (1.f - z) * n + z * hold;
      hw[tid] = hnew;
      hpw[tid] = __float2half(hnew);
    }
    __syncthreads();
  }

  if (rank == 0 && tid < 256) g_hT[bidx * Hh + tid] = h0[tid];

  asm volatile("barrier.cluster.arrive.aligned;" ::: "memory");
  asm volatile("barrier.cluster.wait.aligned;" ::: "memory");
}

// ---------------------------------------------------------------------------
// K6: head.
// ---------------------------------------------------------------------------
__global__ __launch_bounds__(96) void head_kernel(
    const float* __restrict__ head_w, const float* __restrict__ head_b,
    float* __restrict__ out) {
  const int b = blockIdx.x;
  const int o = threadIdx.x;
  const float* h = g_hT + b * Hh;
  const float* wr = head_w + o * Hh;
  float acc = 0.f;
#pragma unroll 8
  for (int k = 0; k < Hh; k++) acc += h[k] * wr[k];
  out[b * HORd + o] = acc + head_b[o];
}

// ---------------------------------------------------------------------------
extern "C" void kernel_launch(void* const* d_in, const int* in_sizes, int n_in,
                              void* d_out, int out_size) {
  const float* x      = (const float*)d_in[0];
  const float* snn_w  = (const float*)d_in[1];
  const float* snn_b  = (const float*)d_in[2];
  const float* wih    = (const float*)d_in[3];
  const float* whh    = (const float*)d_in[4];
  const float* bih    = (const float*)d_in[5];
  const float* bhh    = (const float*)d_in[6];
  const float* head_w = (const float*)d_in[7];
  const float* head_b = (const float*)d_in[8];
  float* out = (float*)d_out;

  cur_gemm_kernel<<<dim3(BT / 128, Hh / 64), 256>>>(x, snn_w, snn_b);
  xcvt_kernel<<<BT * 8 / 256, 256>>>(x);
  wcvt_kernel<<<G3 * KA / 8 / 256, 256>>>(wih);
  lif_kernel<<<Bb, 256>>>();
  gx_mma_kernel<<<dim3(G3 / 64, BT / 128), 256>>>(bih);
  gru_kernel<<<Bb * 2, GRU_THREADS>>>(whh, bhh);
  head_kernel<<<Bb, HORd>>>(head_w, head_b, out);
}

// round 15
// speedup vs baseline: 2.3227x; 1.0673x over previous
#include <cuda_runtime.h>
#include <cuda_bf16.h>
#include <cuda_fp16.h>
#include <cstdint>

// ---------------------------------------------------------------------------
// HybridForecaster: SNN(LIF) -> GRU -> linear head
// B=64, T=2048, C=64, H=256, HOR=96, BETA=0.9, THR=1.0
// R14: GRU k-split across the cluster. 768 thr/CTA (24 warps), thread = one
//      gate row x own 128-k half (80 k in 40 half2 regs + 48 k in smem).
//      Exchange fp32 PARTIAL SUMS via DSMEM+mbarrier; h stays CTA-local.
// ---------------------------------------------------------------------------

#define Bb   64
#define Tt   2048
#define Cc   64
#define Hh   256
#define G3   768
#define KA   320
#define HORd 96
#define BT   (Bb * Tt)

__device__ float g_cur[(size_t)BT * Hh];
__device__ __nv_bfloat16 g_a [(size_t)BT * KA];
__device__ __nv_bfloat16 g_al[(size_t)BT * Cc];
__device__ __nv_bfloat16 g_wh[(size_t)G3 * KA];
__device__ __nv_bfloat16 g_wl[(size_t)G3 * KA];
__device__ float g_gx [(size_t)BT * G3];
__device__ float g_hT [Bb * Hh];

// ------------------------- helpers -----------------------------------------
__device__ __forceinline__ unsigned smem_u32(const void* p) {
  return (unsigned)__cvta_generic_to_shared(p);
}
__device__ __forceinline__ void bfsplit(float x, __nv_bfloat16& hi,
                                        __nv_bfloat16& lo) {
  hi = __float2bfloat16(x);
  lo = __float2bfloat16(x - __bfloat162float(hi));
}

// ---------------------------------------------------------------------------
// K1: cur = x @ snn_w^T + snn_b  (fp32 — feeds threshold logic)
// ---------------------------------------------------------------------------
__global__ __launch_bounds__(256) void cur_gemm_kernel(
    const float* __restrict__ x, const float* __restrict__ w,
    const float* __restrict__ bias) {
  __shared__ float As[32][130];
  __shared__ float Bs[32][66];
  const int row0 = blockIdx.x * 128;
  const int col0 = blockIdx.y * 64;
  const int tid  = threadIdx.x;
  const int tm   = tid & 15;
  const int tn   = tid >> 4;
  float acc[8][4];
#pragma unroll
  for (int i = 0; i < 8; i++)
#pragma unroll
    for (int j = 0; j < 4; j++) acc[i][j] = 0.f;

  const int lm = tid >> 3;
  const int lk = (tid & 7) << 2;

  for (int k0 = 0; k0 < 64; k0 += 32) {
#pragma unroll
    for (int i = 0; i < 4; i++) {
      int m = lm + 32 * i;
      float4 v = *reinterpret_cast<const float4*>(
          &x[(size_t)(row0 + m) * Cc + k0 + lk]);
      As[lk + 0][m] = v.x; As[lk + 1][m] = v.y;
      As[lk + 2][m] = v.z; As[lk + 3][m] = v.w;
    }
#pragma unroll
    for (int i = 0; i < 2; i++) {
      int n = lm + 32 * i;
      float4 v = *reinterpret_cast<const float4*>(
          &w[(size_t)(col0 + n) * Cc + k0 + lk]);
      Bs[lk + 0][n] = v.x; Bs[lk + 1][n] = v.y;
      Bs[lk + 2][n] = v.z; Bs[lk + 3][n] = v.w;
    }
    __syncthreads();
#pragma unroll
    for (int kk = 0; kk < 32; kk++) {
      float a[8], b[4];
#pragma unroll
      for (int i = 0; i < 8; i++) a[i] = As[kk][tm + 16 * i];
#pragma unroll
      for (int j = 0; j < 4; j++) b[j] = Bs[kk][tn * 4 + j];
#pragma unroll
      for (int i = 0; i < 8; i++)
#pragma unroll
        for (int j = 0; j < 4; j++) acc[i][j] += a[i] * b[j];
    }
    __syncthreads();
  }
  float4 bv = *reinterpret_cast<const float4*>(&bias[col0 + tn * 4]);
#pragma unroll
  for (int i = 0; i < 8; i++) {
    float4 o;
    o.x = acc[i][0] + bv.x; o.y = acc[i][1] + bv.y;
    o.z = acc[i][2] + bv.z; o.w = acc[i][3] + bv.w;
    *reinterpret_cast<float4*>(
        &g_cur[(size_t)(row0 + tm + 16 * i) * Hh + col0 + tn * 4]) = o;
  }
}

// ---------------------------------------------------------------------------
// K2a: x -> bf16 hi into g_a[:,0:64], lo into g_al
// ---------------------------------------------------------------------------
__global__ __launch_bounds__(256) void xcvt_kernel(const float* __restrict__ x) {
  int idx8 = blockIdx.x * 256 + threadIdx.x;
  int row = idx8 >> 3;
  int c8  = (idx8 & 7) << 3;
  float v[8];
  *reinterpret_cast<float4*>(v) =
      *reinterpret_cast<const float4*>(&x[(size_t)row * Cc + c8]);
  *reinterpret_cast<float4*>(v + 4) =
      *reinterpret_cast<const float4*>(&x[(size_t)row * Cc + c8 + 4]);
  __nv_bfloat16 hi[8], lo[8];
#pragma unroll
  for (int i = 0; i < 8; i++) bfsplit(v[i], hi[i], lo[i]);
  *reinterpret_cast<uint4*>(&g_a [(size_t)row * KA + c8]) =
      *reinterpret_cast<uint4*>(hi);
  *reinterpret_cast<uint4*>(&g_al[(size_t)row * Cc + c8]) =
      *reinterpret_cast<uint4*>(lo);
}

// K2b: wih -> bf16 hi/lo
__global__ __launch_bounds__(256) void wcvt_kernel(
    const float* __restrict__ wih) {
  int idx8 = blockIdx.x * 256 + threadIdx.x;
  int base = idx8 << 3;
  float v[8];
  *reinterpret_cast<float4*>(v) =
      *reinterpret_cast<const float4*>(&wih[base]);
  *reinterpret_cast<float4*>(v + 4) =
      *reinterpret_cast<const float4*>(&wih[base + 4]);
  __nv_bfloat16 hi[8], lo[8];
#pragma unroll
  for (int i = 0; i < 8; i++) bfsplit(v[i], hi[i], lo[i]);
  *reinterpret_cast<uint4*>(&g_wh[base]) = *reinterpret_cast<uint4*>(hi);
  *reinterpret_cast<uint4*>(&g_wl[base]) = *reinterpret_cast<uint4*>(lo);
}

// ---------------------------------------------------------------------------
// K3: LIF scan -> bf16 spikes into g_a[:,64:320]  (64 blocks x 256 thr)
// ---------------------------------------------------------------------------
__global__ __launch_bounds__(256) void lif_kernel() {
  const int b = blockIdx.x;
  const int h = threadIdx.x;
  const float* cp = g_cur + (size_t)b * Tt * Hh + h;
  __nv_bfloat16* sp = g_a + (size_t)b * Tt * KA + 64 + h;
  const __nv_bfloat16 one = __float2bfloat16(1.0f);
  const __nv_bfloat16 zero = __float2bfloat16(0.0f);
  float mem = 0.f;
#pragma unroll 1
  for (int t = 0; t < Tt; t += 16) {
    float v[16];
#pragma unroll
    for (int i = 0; i < 16; i++) v[i] = __ldcs(cp + (size_t)(t + i) * Hh);
#pragma unroll
    for (int i = 0; i < 16; i++) {
      float reset = (mem > 1.0f) ? 1.0f : 0.0f;
      mem = 0.9f * mem + v[i] - reset;
      sp[(size_t)(t + i) * KA] = (mem > 1.0f) ? one : zero;
    }
  }
}

// ---------------------------------------------------------------------------
// K4: gx split-precision MMA (M=BT, N=768, K=320)  [unchanged from R11]
// ---------------------------------------------------------------------------
#define APAD 40
__global__ __launch_bounds__(256) void gx_mma_kernel(
    const float* __restrict__ bih) {
  __shared__ __nv_bfloat16 As [128][APAD];
  __shared__ __nv_bfloat16 Asl[128][APAD];
  __shared__ __nv_bfloat16 Bh [64][APAD];
  __shared__ __nv_bfloat16 Bl [64][APAD];
  const int col0 = blockIdx.x * 64;
  const int row0 = blockIdx.y * 128;
  const int tid  = threadIdx.x;
  const int warp = tid >> 5;
  const int lane = tid & 31;
  const int wm = warp & 3;
  const int wn = warp >> 2;

  float acc[2][4][4];
#pragma unroll
  for (int mi = 0; mi < 2; mi++)
#pragma unroll
    for (int ni = 0; ni < 4; ni++)
#pragma unroll
      for (int r = 0; r < 4; r++) acc[mi][ni][r] = 0.f;

  const int lmat = lane >> 3, lr = lane & 7;
  const int a_row_base = wm * 32 + lr + (lmat & 1) * 8;
  const int a_col_off  = (lmat >> 1) * 8;
  const int b_row_base = wn * 32 + (lmat >> 1) * 8 + lr;
  const int b_col_off  = (lmat & 1) * 8;

  uint4 rga[2], rgal[2], rgbh, rgbl;
  const int gr = tid >> 2, gqc = tid & 3;
  auto loadg = [&](int kt) {
    int k0 = kt * 32;
#pragma unroll
    for (int i = 0; i < 2; i++) {
      int q = tid + i * 256;
      int r = q >> 2, qc = q & 3;
      rga[i] = *reinterpret_cast<const uint4*>(
          &g_a[(size_t)(row0 + r) * KA + k0 + qc * 8]);
      if (kt < 2)
        rgal[i] = *reinterpret_cast<const uint4*>(
            &g_al[(size_t)(row0 + r) * Cc + k0 + qc * 8]);
    }
    rgbh = *reinterpret_cast<const uint4*>(
        &g_wh[(size_t)(col0 + gr) * KA + k0 + gqc * 8]);
    rgbl = *reinterpret_cast<const uint4*>(
        &g_wl[(size_t)(col0 + gr) * KA + k0 + gqc * 8]);
  };

  loadg(0);
#pragma unroll 1
  for (int kt = 0; kt < 10; kt++) {
    __syncthreads();
#pragma unroll
    for (int i = 0; i < 2; i++) {
      int q = tid + i * 256;
      int r = q >> 2, qc = q & 3;
      *reinterpret_cast<uint4*>(&As[r][qc * 8]) = rga[i];
      if (kt < 2) *reinterpret_cast<uint4*>(&Asl[r][qc * 8]) = rgal[i];
    }
    *reinterpret_cast<uint4*>(&Bh[gr][gqc * 8]) = rgbh;
    *reinterpret_cast<uint4*>(&Bl[gr][gqc * 8]) = rgbl;
    __syncthreads();
    if (kt < 9) loadg(kt + 1);

#pragma unroll
    for (int k0 = 0; k0 < 32; k0 += 16) {
      unsigned a[2][4], bh[2][4], bl[2][4];
#pragma unroll
      for (int mi = 0; mi < 2; mi++) {
        unsigned addr = smem_u32(&As[a_row_base + mi * 16][k0 + a_col_off]);
        asm volatile(
            "ldmatrix.sync.aligned.m8n8.x4.shared.b16 {%0,%1,%2,%3}, [%4];"
            : "=r"(a[mi][0]), "=r"(a[mi][1]), "=r"(a[mi][2]), "=r"(a[mi][3])
            : "r"(addr));
      }
#pragma unroll
      for (int np = 0; np < 2; np++) {
        unsigned addr = smem_u32(&Bh[b_row_base + np * 16][k0 + b_col_off]);
        asm volatile(
            "ldmatrix.sync.aligned.m8n8.x4.shared.b16 {%0,%1,%2,%3}, [%4];"
            : "=r"(bh[np][0]), "=r"(bh[np][1]), "=r"(bh[np][2]),
              "=r"(bh[np][3])
            : "r"(addr));
        unsigned addr2 = smem_u32(&Bl[b_row_base + np * 16][k0 + b_col_off]);
        asm volatile(
            "ldmatrix.sync.aligned.m8n8.x4.shared.b16 {%0,%1,%2,%3}, [%4];"
            : "=r"(bl[np][0]), "=r"(bl[np][1]), "=r"(bl[np][2]),
              "=r"(bl[np][3])
            : "r"(addr2));
      }
#pragma unroll
      for (int mi = 0; mi < 2; mi++)
#pragma unroll
        for (int ni = 0; ni < 4; ni++) {
          unsigned h0r = bh[ni >> 1][(ni & 1) * 2 + 0];
          unsigned h1r = bh[ni >> 1][(ni & 1) * 2 + 1];
          asm volatile(
              "mma.sync.aligned.m16n8k16.row.col.f32.bf16.bf16.f32 "
              "{%0,%1,%2,%3}, {%4,%5,%6,%7}, {%8,%9}, {%0,%1,%2,%3};"
              : "+f"(acc[mi][ni][0]), "+f"(acc[mi][ni][1]),
                "+f"(acc[mi][ni][2]), "+f"(acc[mi][ni][3])
              : "r"(a[mi][0]), "r"(a[mi][1]), "r"(a[mi][2]), "r"(a[mi][3]),
                "r"(h0r), "r"(h1r));
          unsigned l0 = bl[ni >> 1][(ni & 1) * 2 + 0];
          unsigned l1 = bl[ni >> 1][(ni & 1) * 2 + 1];
          asm volatile(
              "mma.sync.aligned.m16n8k16.row.col.f32.bf16.bf16.f32 "
              "{%0,%1,%2,%3}, {%4,%5,%6,%7}, {%8,%9}, {%0,%1,%2,%3};"
              : "+f"(acc[mi][ni][0]), "+f"(acc[mi][ni][1]),
                "+f"(acc[mi][ni][2]), "+f"(acc[mi][ni][3])
              : "r"(a[mi][0]), "r"(a[mi][1]), "r"(a[mi][2]), "r"(a[mi][3]),
                "r"(l0), "r"(l1));
        }
      if (kt < 2) {
        unsigned al[2][4];
#pragma unroll
        for (int mi = 0; mi < 2; mi++) {
          unsigned addr =
              smem_u32(&Asl[a_row_base + mi * 16][k0 + a_col_off]);
          asm volatile(
              "ldmatrix.sync.aligned.m8n8.x4.shared.b16 {%0,%1,%2,%3}, [%4];"
              : "=r"(al[mi][0]), "=r"(al[mi][1]), "=r"(al[mi][2]),
                "=r"(al[mi][3])
              : "r"(addr));
        }
#pragma unroll
        for (int mi = 0; mi < 2; mi++)
#pragma unroll
          for (int ni = 0; ni < 4; ni++) {
            unsigned h0r = bh[ni >> 1][(ni & 1) * 2 + 0];
            unsigned h1r = bh[ni >> 1][(ni & 1) * 2 + 1];
            asm volatile(
                "mma.sync.aligned.m16n8k16.row.col.f32.bf16.bf16.f32 "
                "{%0,%1,%2,%3}, {%4,%5,%6,%7}, {%8,%9}, {%0,%1,%2,%3};"
                : "+f"(acc[mi][ni][0]), "+f"(acc[mi][ni][1]),
                  "+f"(acc[mi][ni][2]), "+f"(acc[mi][ni][3])
                : "r"(al[mi][0]), "r"(al[mi][1]), "r"(al[mi][2]),
                  "r"(al[mi][3]), "r"(h0r), "r"(h1r));
          }
      }
    }
  }

  const int gp = lane >> 2, tg = lane & 3;
#pragma unroll
  for (int mi = 0; mi < 2; mi++) {
#pragma unroll
    for (int ni = 0; ni < 4; ni++) {
      int col = col0 + wn * 32 + ni * 8 + tg * 2;
      float bx = bih[col], by = bih[col + 1];
      int r0 = row0 + wm * 32 + mi * 16 + gp;
      float2 o0 = {acc[mi][ni][0] + bx, acc[mi][ni][1] + by};
      float2 o1 = {acc[mi][ni][2] + bx, acc[mi][ni][3] + by};
      *reinterpret_cast<float2*>(&g_gx[(size_t)r0 * G3 + col]) = o0;
      *reinterpret_cast<float2*>(&g_gx[(size_t)(r0 + 8) * G3 + col]) = o1;
    }
  }
}

// ---------------------------------------------------------------------------
// K5: GRU scan, k-split cluster(2)/batch, 768 threads/CTA.
// Thread tid = gate row j (0..767), k-range = [rank*128, rank*128+128).
// Weights: k-local [0,80) in 40 half2 regs; [80,128) in smem wq[6][768]
// (16B stride -> conflict-free LDS.128). h (own 128 dims) fp16, broadcast.
// Partial = dot (+ gx + bhh on rank0, gx separate for n-rows) shipped to
// the gate-owning CTA via st.shared::cluster + mbarrier(count 768).
// Gate threads (tid<128) combine partials in fp32, update LOCAL h only.
// ---------------------------------------------------------------------------
#define GRU_THREADS 768
#define WQ_OFF   0
#define WQ_SZ    (6 * 768 * 16)                 // 73728
#define PART_OFF (WQ_OFF + WQ_SZ)               // part[2buf][2src][384] f32
#define PART_SZ  (2 * 2 * 384 * 4)              // 6144
#define XN_OFF   (PART_OFF + PART_SZ)           // xn[2buf][128] f32
#define XN_SZ    (2 * 128 * 4)                  // 1024
#define H32_OFF  (XN_OFF + XN_SZ)               // 512
#define HP_OFF   (H32_OFF + 512)                // hp[2buf][128] half = 512
#define MB_OFF   (HP_OFF + 512)
#define GRU_SMEM (MB_OFF + 16)                  // ~82 KB

extern __shared__ char gsm[];

__global__ void __cluster_dims__(2, 1, 1) __launch_bounds__(GRU_THREADS, 1)
gru_kernel(const float* __restrict__ whh, const float* __restrict__ bhh) {
  const int tid = threadIdx.x;                  // = gate row j
  unsigned rank_u;
  asm("mov.u32 %0, %%cluster_ctarank;" : "=r"(rank_u));
  const int rank = (int)rank_u;
  const int bidx = blockIdx.x >> 1;
  const int j = tid;
  const int k0 = rank * 128;
  const int l = (j >> 8) * 128 + (j & 127);     // slot within 384
  const int dest = (j >> 7) & 1;                // CTA owning this row's gate

  const float* wr = whh + (size_t)j * 256 + k0;

  // 80 k in 40 half2 regs
  __half2 w16[40];
#pragma unroll
  for (int i = 0; i < 10; i++) {
    float4 a = *reinterpret_cast<const float4*>(wr + i * 8);
    float4 b = *reinterpret_cast<const float4*>(wr + i * 8 + 4);
    w16[4 * i + 0] = __floats2half2_rn(a.x, a.y);
    w16[4 * i + 1] = __floats2half2_rn(a.z, a.w);
    w16[4 * i + 2] = __floats2half2_rn(b.x, b.y);
    w16[4 * i + 3] = __floats2half2_rn(b.z, b.w);
  }
  // 48 k in smem: wq[q][tid], q=0..5, 16B stride (conflict-free)
  unsigned* wq = reinterpret_cast<unsigned*>(gsm + WQ_OFF);
#pragma unroll
  for (int q = 0; q < 6; q++) {
    float4 a = *reinterpret_cast<const float4*>(wr + 80 + q * 8);
    float4 b = *reinterpret_cast<const float4*>(wr + 80 + q * 8 + 4);
    __half2 p0 = __floats2half2_rn(a.x, a.y);
    __half2 p1 = __floats2half2_rn(a.z, a.w);
    __half2 p2 = __floats2half2_rn(b.x, b.y);
    __half2 p3 = __floats2half2_rn(b.z, b.w);
    uint4 pk;
    pk.x = *reinterpret_cast<unsigned*>(&p0);
    pk.y = *reinterpret_cast<unsigned*>(&p1);
    pk.z = *reinterpret_cast<unsigned*>(&p2);
    pk.w = *reinterpret_cast<unsigned*>(&p3);
    *reinterpret_cast<uint4*>(&wq[(q * 768 + tid) * 4]) = pk;
  }

  float* part = reinterpret_cast<float*>(gsm + PART_OFF);
  float* xnA  = reinterpret_cast<float*>(gsm + XN_OFF);
  float* h32  = reinterpret_cast<float*>(gsm + H32_OFF);
  __half* hpb = reinterpret_cast<__half*>(gsm + HP_OFF);

  const float bh = (rank == 0) ? bhh[j] : 0.f;
  if (tid < 128) { h32[tid] = 0.f; hpb[tid] = __float2half(0.f); }

  const unsigned mb_base = smem_u32(gsm + MB_OFF);
  if (tid == 0) {
    asm volatile("mbarrier.init.shared.b64 [%0], %1;" ::"r"(mb_base),
                 "r"(768u) : "memory");
    asm volatile("mbarrier.init.shared.b64 [%0], %1;" ::"r"(mb_base + 8),
                 "r"(768u) : "memory");
  }

  // publish addresses (buf0; buf1 = +fixed byte offsets), via mapa to dest
  unsigned paddr0, xaddr0, marr;
  {
    unsigned lp = smem_u32(gsm + PART_OFF) + (unsigned)(rank * 384 + l) * 4u;
    asm volatile("mapa.shared::cluster.u32 %0, %1, %2;"
                 : "=r"(paddr0) : "r"(lp), "r"(dest));
    unsigned lx = smem_u32(gsm + XN_OFF) + (unsigned)(j & 127) * 4u;
    asm volatile("mapa.shared::cluster.u32 %0, %1, %2;"
                 : "=r"(xaddr0) : "r"(lx), "r"(dest));
    asm volatile("mapa.shared::cluster.u32 %0, %1, %2;"
                 : "=r"(marr) : "r"(mb_base), "r"(dest));
  }

  __syncthreads();
  asm volatile("barrier.cluster.arrive.aligned;" ::: "memory");
  asm volatile("barrier.cluster.wait.aligned;" ::: "memory");

  const float* gxp = g_gx + (size_t)bidx * Tt * G3 + j;
  float gxv = (rank == 0) ? __ldcg(gxp) : 0.f;

  int ph0 = 0, ph1 = 0;

#pragma unroll 1
  for (int t = 0; t < Tt; t++) {
    const int buf = t & 1;
    float gxnext = (rank == 0 && t + 1 < Tt)
                       ? __ldcg(gxp + (size_t)(t + 1) * G3) : 0.f;

    // ---- partial dot over own k-half: 16 h-LDS(bcast) + 6 w-LDS + 64 HFMA2
    const uint4* hp4 = reinterpret_cast<const uint4*>(hpb + buf * 128);
    __half2 hc0 = __float2half2_rn(0.f), hc1 = hc0, hc2 = hc0, hc3 = hc0;
#pragma unroll
    for (int i = 0; i < 10; i++) {
      uint4 hv = hp4[i];
      hc0 = __hfma2(w16[4 * i + 0], *reinterpret_cast<__half2*>(&hv.x), hc0);
      hc1 = __hfma2(w16[4 * i + 1], *reinterpret_cast<__half2*>(&hv.y), hc1);
      hc2 = __hfma2(w16[4 * i + 2], *reinterpret_cast<__half2*>(&hv.z), hc2);
      hc3 = __hfma2(w16[4 * i + 3], *reinterpret_cast<__half2*>(&hv.w), hc3);
    }
#pragma unroll
    for (int q = 0; q < 6; q++) {
      uint4 wv = *reinterpret_cast<const uint4*>(&wq[(q * 768 + tid) * 4]);
      uint4 hv = hp4[10 + q];
      hc0 = __hfma2(*reinterpret_cast<__half2*>(&wv.x),
                    *reinterpret_cast<__half2*>(&hv.x), hc0);
      hc1 = __hfma2(*reinterpret_cast<__half2*>(&wv.y),
                    *reinterpret_cast<__half2*>(&hv.y), hc1);
      hc2 = __hfma2(*reinterpret_cast<__half2*>(&wv.z),
                    *reinterpret_cast<__half2*>(&hv.z), hc2);
      hc3 = __hfma2(*reinterpret_cast<__half2*>(&wv.w),
                    *reinterpret_cast<__half2*>(&hv.w), hc3);
    }
    float2 f0 = __half22float2(hc0);
    float2 f1 = __half22float2(hc1);
    float2 f2 = __half22float2(hc2);
    float2 f3 = __half22float2(hc3);
    float s = ((f0.x + f0.y) + (f1.x + f1.y)) +
              ((f2.x + f2.y) + (f3.x + f3.y)) + bh;
    if (rank == 0 && j < 512) s += gxv;   // fold gx into r/z partials

    // ---- publish partial (+ xn for n-rows from rank0) to dest CTA ----
    const unsigned pb = paddr0 + (unsigned)buf * 3072u;
    asm volatile("st.shared::cluster.f32 [%0], %1;"
                 :: "r"(pb), "f"(s) : "memory");
    if (rank == 0 && j >= 512) {
      asm volatile("st.shared::cluster.f32 [%0], %1;"
                   :: "r"(xaddr0 + (unsigned)buf * 512u), "f"(gxv)
                   : "memory");
    }
    asm volatile("mbarrier.arrive.release.cluster.shared::cluster.b64 _, [%0];"
                 :: "r"(marr + 8u * (unsigned)buf) : "memory");
    gxv = gxnext;

    // ---- wait for all 768 partials for this CTA's gate dims ----
    {
      unsigned mb = mb_base + 8u * (unsigned)buf;
      unsigned par = (unsigned)(buf ? ph1 : ph0);
      asm volatile(
          "{\n\t.reg .pred P1;\n\t"
          "GRUW_%=:\n\t"
          "mbarrier.try_wait.parity.acquire.cluster.shared::cta.b64 P1, [%0], "
          "%1;\n\t"
          "@P1 bra GRUD_%=;\n\t"
          "bra GRUW_%=;\n\t"
          "GRUD_%=:\n\t}"
          :: "r"(mb), "r"(par) : "memory");
      if (buf) ph1 ^= 1; else ph0 ^= 1;
    }

    // ---- gate math on own 128 dims (local h only) ----
    if (tid < 128) {
      const float* pl = part + buf * 768;       // [src0 384][src1 384]
      float sr  = pl[tid]       + pl[384 + tid];
      float sz  = pl[128 + tid] + pl[384 + 128 + tid];
      float hnp = pl[256 + tid] + pl[384 + 256 + tid];
      float xnv = xnA[buf * 128 + tid];
      float r = 1.f / (1.f + __expf(-sr));
      float z = 1.f / (1.f + __expf(-sz));
      float y = xnv + r * hnp;
      float e = __expf(2.f * y);
      float n = 1.f - __fdividef(2.f, e + 1.f);
      float hold = h32[tid];
      float hnew = (1.f - z) * n + z * hold;
      h32[tid] = hnew;
      hpb[((t + 1) & 1) * 128 + tid] = __float2half(hnew);
    }
    __syncthreads();
  }

  if (tid < 128) g_hT[bidx * Hh + rank * 128 + tid] = h32[tid];

  asm volatile("barrier.cluster.arrive.aligned;" ::: "memory");
  asm volatile("barrier.cluster.wait.aligned;" ::: "memory");
}

// ---------------------------------------------------------------------------
// K6: head.
// ---------------------------------------------------------------------------
__global__ __launch_bounds__(96) void head_kernel(
    const float* __restrict__ head_w, const float* __restrict__ head_b,
    float* __restrict__ out) {
  const int b = blockIdx.x;
  const int o = threadIdx.x;
  const float* h = g_hT + b * Hh;
  const float* wr = head_w + o * Hh;
  float acc = 0.f;
#pragma unroll 8
  for (int k = 0; k < Hh; k++) acc += h[k] * wr[k];
  out[b * HORd + o] = acc + head_b[o];
}

// ---------------------------------------------------------------------------
extern "C" void kernel_launch(void* const* d_in, const int* in_sizes, int n_in,
                              void* d_out, int out_size) {
  const float* x      = (const float*)d_in[0];
  const float* snn_w  = (const float*)d_in[1];
  const float* snn_b  = (const float*)d_in[2];
  const float* wih    = (const float*)d_in[3];
  const float* whh    = (const float*)d_in[4];
  const float* bih    = (const float*)d_in[5];
  const float* bhh    = (const float*)d_in[6];
  const float* head_w = (const float*)d_in[7];
  const float* head_b = (const float*)d_in[8];
  float* out = (float*)d_out;

  cudaFuncSetAttribute(gru_kernel,
                       cudaFuncAttributeMaxDynamicSharedMemorySize, GRU_SMEM);

  cur_gemm_kernel<<<dim3(BT / 128, Hh / 64), 256>>>(x, snn_w, snn_b);
  xcvt_kernel<<<BT * 8 / 256, 256>>>(x);
  wcvt_kernel<<<G3 * KA / 8 / 256, 256>>>(wih);
  lif_kernel<<<Bb, 256>>>();
  gx_mma_kernel<<<dim3(G3 / 64, BT / 128), 256>>>(bih);
  gru_kernel<<<Bb * 2, GRU_THREADS, GRU_SMEM>>>(whh, bhh);
  head_kernel<<<Bb, HORd>>>(head_w, head_b, out);
}